// round 1
// baseline (speedup 1.0000x reference)
#include <cuda_runtime.h>

// Problem constants
#define Bq 32
#define Cc 64
#define Nn 1024

typedef unsigned long long ull;

// ---------------- scratch (device globals: no allocation allowed) -----------
__device__ float g_phi[Bq * Cc * Nn];     // [b][c][n]   phi = w_phi @ x
__device__ float g_theta[Bq * Cc * Nn];   // [b][c][n]   theta^T (theta[n,c] stored [c][n])
__device__ float g_gm[Bq * Cc * Nn];      // [b][c][n]   (w_mv @ w_g) @ x
__device__ float g_P[Bq * Cc * Nn];       // [b][c][k]   P = phi @ w_mk^T
__device__ float g_E[Bq * Nn * Nn];       // [b][n][k]   exp(att)   (128 MB)
__device__ float g_Z[Bq * Nn];            // column sums of exp(att) over n
__device__ float g_wgv[Cc * Cc];          // w_mv @ w_g

// ---------------- f32x2 helpers (full-rate fp32 on sm_103a) -----------------
__device__ __forceinline__ ull pk2(float lo, float hi) {
    ull r;
    asm("mov.b64 %0, {%1, %2};" : "=l"(r) : "f"(lo), "f"(hi));
    return r;
}
__device__ __forceinline__ void fma2(ull& d, ull a, ull b) {
    asm("fma.rn.f32x2 %0, %1, %2, %0;" : "+l"(d) : "l"(a), "l"(b));
}
__device__ __forceinline__ float2 upk2(ull v) {
    float2 r;
    asm("mov.b64 {%0, %1}, %2;" : "=f"(r.x), "=f"(r.y) : "l"(v));
    return r;
}

// 8 packed FMAs = 16 scalar FMAs on a 4x4 micro-tile
#define MICRO_FMA(acc, av, bv)                                   \
    do {                                                         \
        ull a0 = pk2(av.x, av.x), a1 = pk2(av.y, av.y);          \
        ull a2 = pk2(av.z, av.z), a3 = pk2(av.w, av.w);          \
        fma2(acc[0][0], a0, bv.x); fma2(acc[0][1], a0, bv.y);    \
        fma2(acc[1][0], a1, bv.x); fma2(acc[1][1], a1, bv.y);    \
        fma2(acc[2][0], a2, bv.x); fma2(acc[2][1], a2, bv.y);    \
        fma2(acc[3][0], a3, bv.x); fma2(acc[3][1], a3, bv.y);    \
    } while (0)

// ---------------- K0: zero Z, combine w_gv = w_mv @ w_g ---------------------
__global__ void k0_prep(const float* __restrict__ wmv, const float* __restrict__ wg) {
    int t = blockIdx.x * blockDim.x + threadIdx.x;
    if (t < Bq * Nn) g_Z[t] = 0.0f;
    if (t < Cc * Cc) {
        int d = t >> 6, ci = t & 63;
        float s = 0.0f;
#pragma unroll
        for (int c = 0; c < 64; c++) s += wmv[d * 64 + c] * wg[c * 64 + ci];
        g_wgv[t] = s;
    }
}

// ---------------- K1: channel GEMMs: phi, theta^T, gm -----------------------
// grid (B, N/64), block 256.  out[c][n] = sum_ci W[c][ci] * x[ci][n]
__global__ __launch_bounds__(256) void k1_channel(
    const float* __restrict__ x, const float* __restrict__ wphi,
    const float* __restrict__ wtheta) {
    __shared__ __align__(16) float sX[64][68];   // [ci][nn]
    __shared__ __align__(16) float sW[64][68];   // [ci][c]  (transposed weight)
    int b = blockIdx.x, n0 = blockIdx.y << 6;
    int t = threadIdx.x;
    int ty = t >> 4, tx = t & 15;

#pragma unroll
    for (int i = 0; i < 16; i++) {
        int idx = t + (i << 8);
        int ci = idx >> 6, nn = idx & 63;
        sX[ci][nn] = x[((b << 6) + ci) * Nn + n0 + nn];
    }

    const float* Ws[3] = {wphi, wtheta, g_wgv};
    float* Os[3] = {g_phi, g_theta, g_gm};

    for (int p = 0; p < 3; p++) {
        __syncthreads();
#pragma unroll
        for (int i = 0; i < 16; i++) {
            int idx = t + (i << 8);
            int c = idx >> 6, ci = idx & 63;
            sW[ci][c] = Ws[p][idx];
        }
        __syncthreads();

        ull acc[4][2] = {};
#pragma unroll 8
        for (int ci = 0; ci < 64; ci++) {
            float4 av = *(const float4*)&sW[ci][ty << 2];
            ulonglong2 bv = *(const ulonglong2*)&sX[ci][tx << 2];
            MICRO_FMA(acc, av, bv);
        }
        float* O = Os[p] + (b << 6) * Nn + n0;
#pragma unroll
        for (int i = 0; i < 4; i++) {
            float2 v0 = upk2(acc[i][0]), v1 = upk2(acc[i][1]);
            *(float4*)&O[((ty << 2) + i) * Nn + (tx << 2)] =
                make_float4(v0.x, v0.y, v1.x, v1.y);
        }
    }
}

// ---------------- K2: P = phi @ w_mk^T --------------------------------------
// grid (B, N/64), block 256.  P[c][k] = sum_m phi[c][m] * wmk[k][m]
__global__ __launch_bounds__(256) void k2_P(const float* __restrict__ wmk) {
    __shared__ __align__(16) float sA[64][68];  // [mm][c]  phi^T chunk
    __shared__ __align__(16) float sB[64][68];  // [mm][kk] wmk^T chunk
    int b = blockIdx.x, k0 = blockIdx.y << 6;
    int t = threadIdx.x, ty = t >> 4, tx = t & 15;
    const float* phi = g_phi + (b << 6) * Nn;

    ull acc[4][2] = {};
    for (int m0 = 0; m0 < Nn; m0 += 64) {
        __syncthreads();
#pragma unroll
        for (int i = 0; i < 16; i++) {
            int idx = t + (i << 8);
            int r = idx >> 6, mm = idx & 63;
            sA[mm][r] = phi[r * Nn + m0 + mm];
            sB[mm][r] = wmk[(k0 + r) * Nn + m0 + mm];
        }
        __syncthreads();
#pragma unroll 8
        for (int mm = 0; mm < 64; mm++) {
            float4 av = *(const float4*)&sA[mm][ty << 2];
            ulonglong2 bv = *(const ulonglong2*)&sB[mm][tx << 2];
            MICRO_FMA(acc, av, bv);
        }
    }
    float* P = g_P + (b << 6) * Nn + k0;
#pragma unroll
    for (int i = 0; i < 4; i++) {
        float2 v0 = upk2(acc[i][0]), v1 = upk2(acc[i][1]);
        *(float4*)&P[((ty << 2) + i) * Nn + (tx << 2)] =
            make_float4(v0.x, v0.y, v1.x, v1.y);
    }
}

// ---------------- K3: E = exp(theta @ P), column sums Z ---------------------
// grid (N/64 k-tiles, N/64 n-tiles, B), block 256.
__global__ __launch_bounds__(256) void k3_att(void) {
    __shared__ __align__(16) float sT[64][68];  // [c][nn] theta^T tile
    __shared__ __align__(16) float sP[64][68];  // [c][kk] P tile
    __shared__ float red[16][64];
    int b = blockIdx.z, n0 = blockIdx.y << 6, k0 = blockIdx.x << 6;
    int t = threadIdx.x, ty = t >> 4, tx = t & 15;
    const float* th = g_theta + (b << 6) * Nn;
    const float* Pp = g_P + (b << 6) * Nn;

#pragma unroll
    for (int i = 0; i < 16; i++) {
        int idx = t + (i << 8);
        int c = idx >> 6, j = idx & 63;
        sT[c][j] = th[c * Nn + n0 + j];
        sP[c][j] = Pp[c * Nn + k0 + j];
    }
    __syncthreads();

    ull acc[4][2] = {};
#pragma unroll 8
    for (int c = 0; c < 64; c++) {
        float4 av = *(const float4*)&sT[c][ty << 2];   // 4 n's
        ulonglong2 bv = *(const ulonglong2*)&sP[c][tx << 2];  // 4 k's
        MICRO_FMA(acc, av, bv);
    }

    // exp + store E + partial column sums (no max subtraction: |att| <~ 50)
    float ps0 = 0.f, ps1 = 0.f, ps2 = 0.f, ps3 = 0.f;
    float* E = g_E + (b * Nn + n0 + (ty << 2)) * Nn + k0 + (tx << 2);
#pragma unroll
    for (int i = 0; i < 4; i++) {
        float2 v0 = upk2(acc[i][0]), v1 = upk2(acc[i][1]);
        float e0 = __expf(v0.x), e1 = __expf(v0.y);
        float e2 = __expf(v1.x), e3 = __expf(v1.y);
        *(float4*)&E[i * Nn] = make_float4(e0, e1, e2, e3);
        ps0 += e0; ps1 += e1; ps2 += e2; ps3 += e3;
    }
    red[ty][(tx << 2) + 0] = ps0;
    red[ty][(tx << 2) + 1] = ps1;
    red[ty][(tx << 2) + 2] = ps2;
    red[ty][(tx << 2) + 3] = ps3;
    __syncthreads();
    if (t < 64) {
        float s = 0.f;
#pragma unroll
        for (int r = 0; r < 16; r++) s += red[r][t];
        atomicAdd(&g_Z[b * Nn + k0 + t], s);
    }
}

// ---------------- K4: out = E @ (gm/Z), fused mask conv + residual ----------
// grid (B, N/64), block 256.
__global__ __launch_bounds__(256) void k4_out(
    const float* __restrict__ x, const float* __restrict__ wmask,
    float* __restrict__ out) {
    __shared__ __align__(16) float s1[64][68];  // sE [mm][nn], later sO [c'][nn]
    __shared__ __align__(16) float s2[64][68];  // sG [mm][c],  later sWm [c'][c]
    int b = blockIdx.x, n0 = blockIdx.y << 6;
    int t = threadIdx.x, ty = t >> 4, tx = t & 15;
    const float* gm = g_gm + (b << 6) * Nn;
    int mym = t & 63;  // each thread only ever loads this mm within a chunk

    ull acc[4][2] = {};
    for (int m0 = 0; m0 < Nn; m0 += 64) {
        __syncthreads();
        float iz = 1.0f / g_Z[b * Nn + m0 + mym];
#pragma unroll
        for (int i = 0; i < 16; i++) {
            int idx = t + (i << 8);
            int r = idx >> 6;
            s2[mym][r] = gm[r * Nn + m0 + mym] * iz;             // gs^T
            s1[mym][r] = g_E[(b * Nn + n0 + r) * Nn + m0 + mym]; // E^T
        }
        __syncthreads();
#pragma unroll 8
        for (int mm = 0; mm < 64; mm++) {
            float4 av = *(const float4*)&s2[mm][ty << 2];        // 4 c's
            ulonglong2 bv = *(const ulonglong2*)&s1[mm][tx << 2];// 4 n's
            MICRO_FMA(acc, av, bv);
        }
    }

    // stage out_t tile [c][nn] to smem, load mask^T
    __syncthreads();
#pragma unroll
    for (int i = 0; i < 4; i++) {
        float2 v0 = upk2(acc[i][0]), v1 = upk2(acc[i][1]);
        *(float4*)&s1[(ty << 2) + i][tx << 2] = make_float4(v0.x, v0.y, v1.x, v1.y);
    }
#pragma unroll
    for (int i = 0; i < 16; i++) {
        int idx = t + (i << 8);
        int c = idx >> 6, cp = idx & 63;
        s2[cp][c] = wmask[idx];
    }
    __syncthreads();

    ull acc2[4][2] = {};
#pragma unroll 8
    for (int cp = 0; cp < 64; cp++) {
        float4 av = *(const float4*)&s2[cp][ty << 2];
        ulonglong2 bv = *(const ulonglong2*)&s1[cp][tx << 2];
        MICRO_FMA(acc2, av, bv);
    }

    // residual add + store
#pragma unroll
    for (int i = 0; i < 4; i++) {
        int c = (ty << 2) + i;
        int off = ((b << 6) + c) * Nn + n0 + (tx << 2);
        float4 xv = *(const float4*)&x[off];
        float2 v0 = upk2(acc2[i][0]), v1 = upk2(acc2[i][1]);
        *(float4*)&out[off] =
            make_float4(v0.x + xv.x, v0.y + xv.y, v1.x + xv.z, v1.y + xv.w);
    }
}

// ---------------- launch ----------------------------------------------------
extern "C" void kernel_launch(void* const* d_in, const int* in_sizes, int n_in,
                              void* d_out, int out_size) {
    const float* x      = (const float*)d_in[0];
    const float* wphi   = (const float*)d_in[1];
    const float* wtheta = (const float*)d_in[2];
    const float* wg     = (const float*)d_in[3];
    const float* wmask  = (const float*)d_in[4];
    const float* wmv    = (const float*)d_in[5];
    const float* wmk    = (const float*)d_in[6];
    float* out = (float*)d_out;

    k0_prep<<<128, 256>>>(wmv, wg);
    k1_channel<<<dim3(32, 16), 256>>>(x, wphi, wtheta);
    k2_P<<<dim3(32, 16), 256>>>(wmk);
    k3_att<<<dim3(16, 16, 32), 256>>>();
    k4_out<<<dim3(32, 16), 256>>>(x, wmask, out);
}

// round 2
// speedup vs baseline: 1.3385x; 1.3385x over previous
#include <cuda_runtime.h>

#define Bq 32
#define Cc 64
#define Nn 1024

typedef unsigned long long ull;

// ---------------- scratch (device globals) ----------------------------------
__device__ float g_phiT[Bq * Nn * Cc];    // [b][m][c]   phi^T
__device__ float g_theta[Bq * Cc * Nn];   // [b][c][n]   theta^T
__device__ float g_gm[Bq * Cc * Nn];      // [b][c][n]   (w_mv@w_g) @ x
__device__ float g_P[Bq * Cc * Nn];       // [b][c][k]   P = phi @ w_mk^T
__device__ float g_E[Bq * Nn * Nn];       // [b][k][n]   exp(att)^T  (128 MB)
__device__ float g_Z[Bq * Nn];            // col sums of exp(att) over n
__device__ float g_wgv[Cc * Cc];          // w_mv @ w_g
__device__ float g_wmkT[Nn * Nn];         // w_mk^T
__device__ float g_gmz2[Bq * Nn * Cc];    // [b][m][o]  (w_mask@gm)/Z folded

// ---------------- f32x2 helpers ---------------------------------------------
__device__ __forceinline__ ull pk2(float lo, float hi) {
    ull r;
    asm("mov.b64 %0, {%1, %2};" : "=l"(r) : "f"(lo), "f"(hi));
    return r;
}
__device__ __forceinline__ void fma2(ull& d, ull a, ull b) {
    asm("fma.rn.f32x2 %0, %1, %2, %0;" : "+l"(d) : "l"(a), "l"(b));
}
__device__ __forceinline__ float2 upk2(ull v) {
    float2 r;
    asm("mov.b64 {%0, %1}, %2;" : "=f"(r.x), "=f"(r.y) : "l"(v));
    return r;
}

// 8 (broadcast scalars) x 8 (packed pairs x4) micro step
#define FMA_ROW8(acc, kv, b0, b1)                                    \
    do {                                                             \
        _Pragma("unroll")                                            \
        for (int _i = 0; _i < 8; _i++) {                             \
            ull _a = pk2(kv[_i], kv[_i]);                            \
            fma2(acc[_i][0], _a, b0.x); fma2(acc[_i][1], _a, b0.y);  \
            fma2(acc[_i][2], _a, b1.x); fma2(acc[_i][3], _a, b1.y);  \
        }                                                            \
    } while (0)

// ---------------- K0: zero Z, wgv = w_mv @ w_g ------------------------------
__global__ void k0_prep(const float* __restrict__ wmv, const float* __restrict__ wg) {
    int t = blockIdx.x * blockDim.x + threadIdx.x;
    if (t < Bq * Nn) g_Z[t] = 0.0f;
    if (t < Cc * Cc) {
        int d = t >> 6, ci = t & 63;
        float s = 0.0f;
#pragma unroll
        for (int c = 0; c < 64; c++) s += wmv[d * 64 + c] * wg[c * 64 + ci];
        g_wgv[t] = s;
    }
}

// ---------------- K0t: wmkT[m][k] = wmk[k][m] -------------------------------
__global__ __launch_bounds__(256) void k0t_transpose(const float* __restrict__ wmk) {
    __shared__ float tl[32][33];
    int r0 = blockIdx.y << 5, c0 = blockIdx.x << 5;
    int t = threadIdx.x, c = t & 31, r = t >> 5;
#pragma unroll
    for (int i = 0; i < 4; i++)
        tl[r + i * 8][c] = wmk[(r0 + r + i * 8) * Nn + c0 + c];
    __syncthreads();
#pragma unroll
    for (int i = 0; i < 4; i++)
        g_wmkT[(c0 + r + i * 8) * Nn + r0 + c] = tl[c][r + i * 8];
}

// ---------------- K1: channel GEMMs: phiT, theta, gm ------------------------
__global__ __launch_bounds__(256) void k1_channel(
    const float* __restrict__ x, const float* __restrict__ wphi,
    const float* __restrict__ wtheta) {
    __shared__ __align__(16) float sX[64][68];   // [ci][nn]
    __shared__ __align__(16) float sW[64][68];   // [ci][c]
    int b = blockIdx.x, n0 = blockIdx.y << 6;
    int t = threadIdx.x, ty = t >> 4, tx = t & 15;

#pragma unroll
    for (int i = 0; i < 16; i++) {
        int idx = t + (i << 8);
        int ci = idx >> 6, nn = idx & 63;
        sX[ci][nn] = x[((b << 6) + ci) * Nn + n0 + nn];
    }

    const float* Ws[3] = {wphi, wtheta, g_wgv};

    for (int p = 0; p < 3; p++) {
        __syncthreads();
#pragma unroll
        for (int i = 0; i < 16; i++) {
            int idx = t + (i << 8);
            int c = idx >> 6, ci = idx & 63;
            sW[ci][c] = Ws[p][idx];
        }
        __syncthreads();

        ull acc[4][2] = {};
#pragma unroll 8
        for (int ci = 0; ci < 64; ci++) {
            float4 av = *(const float4*)&sW[ci][ty << 2];
            ulonglong2 bv = *(const ulonglong2*)&sX[ci][tx << 2];
            ull a0 = pk2(av.x, av.x), a1 = pk2(av.y, av.y);
            ull a2 = pk2(av.z, av.z), a3 = pk2(av.w, av.w);
            fma2(acc[0][0], a0, bv.x); fma2(acc[0][1], a0, bv.y);
            fma2(acc[1][0], a1, bv.x); fma2(acc[1][1], a1, bv.y);
            fma2(acc[2][0], a2, bv.x); fma2(acc[2][1], a2, bv.y);
            fma2(acc[3][0], a3, bv.x); fma2(acc[3][1], a3, bv.y);
        }
        float v[4][4];
#pragma unroll
        for (int i = 0; i < 4; i++) {
            float2 v0 = upk2(acc[i][0]), v1 = upk2(acc[i][1]);
            v[i][0] = v0.x; v[i][1] = v0.y; v[i][2] = v1.x; v[i][3] = v1.y;
        }
        if (p == 0) {
            // phiT[m][c]
#pragma unroll
            for (int j = 0; j < 4; j++) {
                *(float4*)&g_phiT[(b * Nn + n0 + (tx << 2) + j) * Cc + (ty << 2)] =
                    make_float4(v[0][j], v[1][j], v[2][j], v[3][j]);
            }
        } else {
            float* O = (p == 1 ? g_theta : g_gm) + (b << 6) * Nn + n0;
#pragma unroll
            for (int i = 0; i < 4; i++)
                *(float4*)&O[((ty << 2) + i) * Nn + (tx << 2)] =
                    make_float4(v[i][0], v[i][1], v[i][2], v[i][3]);
        }
    }
}

// ---------------- K2: P[c][k] = sum_m phiT[m][c] * wmkT[m][k] ---------------
// grid (B, N/256), block 256, micro 8c x 8k
__global__ __launch_bounds__(256, 2) void k2_P(void) {
    __shared__ __align__(16) float sA[32][68];   // [mm][c]
    __shared__ __align__(16) float sB[32][264];  // [mm][kk], k-tile 256
    int b = blockIdx.x, k0 = blockIdx.y << 8;
    int t = threadIdx.x, cy = t >> 5, kx = t & 31;

    ull acc[8][4] = {};
    for (int m0 = 0; m0 < Nn; m0 += 32) {
        __syncthreads();
#pragma unroll
        for (int i = 0; i < 2; i++) {
            int idx = t + (i << 8);
            int r = idx >> 4, c4 = idx & 15;
            *(float4*)&sA[r][c4 << 2] =
                *(const float4*)&g_phiT[(b * Nn + m0 + r) * Cc + (c4 << 2)];
        }
#pragma unroll
        for (int i = 0; i < 8; i++) {
            int idx = t + (i << 8);
            int r = idx >> 6, c4 = idx & 63;
            *(float4*)&sB[r][c4 << 2] =
                *(const float4*)&g_wmkT[(m0 + r) * Nn + k0 + (c4 << 2)];
        }
        __syncthreads();
#pragma unroll
        for (int mm = 0; mm < 32; mm++) {
            float4 a0 = *(const float4*)&sA[mm][cy << 3];
            float4 a1 = *(const float4*)&sA[mm][(cy << 3) + 4];
            ulonglong2 b0 = *(const ulonglong2*)&sB[mm][kx << 2];
            ulonglong2 b1 = *(const ulonglong2*)&sB[mm][128 + (kx << 2)];
            float kv[8] = {a0.x, a0.y, a0.z, a0.w, a1.x, a1.y, a1.z, a1.w};
            FMA_ROW8(acc, kv, b0, b1);
        }
    }
    float* Pp = g_P + (b << 6) * Nn;
#pragma unroll
    for (int i = 0; i < 8; i++) {
        int c = (cy << 3) + i;
        float2 v0 = upk2(acc[i][0]), v1 = upk2(acc[i][1]);
        float2 v2 = upk2(acc[i][2]), v3 = upk2(acc[i][3]);
        *(float4*)&Pp[c * Nn + k0 + (kx << 2)] = make_float4(v0.x, v0.y, v1.x, v1.y);
        *(float4*)&Pp[c * Nn + k0 + 128 + (kx << 2)] = make_float4(v2.x, v2.y, v3.x, v3.y);
    }
}

// ---------------- K3: E_t[k][n] = exp(sum_c theta[c][n] P[c][k]), Z sums ----
// grid (N/128 k, N/128 n, B), block 256, micro 8k x 8n
__global__ __launch_bounds__(256, 2) void k3_att(void) {
    __shared__ __align__(16) float sP[32][132];  // [cc][kk]
    __shared__ __align__(16) float sT[32][132];  // [cc][nn]
    __shared__ float red[128][17];
    int b = blockIdx.z, n0 = blockIdx.y << 7, k0 = blockIdx.x << 7;
    int t = threadIdx.x, ty = t >> 4, tx = t & 15;
    const float* th = g_theta + (b << 6) * Nn;
    const float* Pp = g_P + (b << 6) * Nn;

    ull acc[8][4] = {};
    for (int c0 = 0; c0 < 64; c0 += 32) {
        __syncthreads();
#pragma unroll
        for (int i = 0; i < 4; i++) {
            int idx = t + (i << 8);
            int r = idx >> 5, c4 = idx & 31;
            *(float4*)&sT[r][c4 << 2] = *(const float4*)&th[(c0 + r) * Nn + n0 + (c4 << 2)];
            *(float4*)&sP[r][c4 << 2] = *(const float4*)&Pp[(c0 + r) * Nn + k0 + (c4 << 2)];
        }
        __syncthreads();
#pragma unroll
        for (int cc = 0; cc < 32; cc++) {
            float4 a0 = *(const float4*)&sP[cc][ty << 3];
            float4 a1 = *(const float4*)&sP[cc][(ty << 3) + 4];
            ulonglong2 b0 = *(const ulonglong2*)&sT[cc][tx << 2];
            ulonglong2 b1 = *(const ulonglong2*)&sT[cc][64 + (tx << 2)];
            float kv[8] = {a0.x, a0.y, a0.z, a0.w, a1.x, a1.y, a1.z, a1.w};
            FMA_ROW8(acc, kv, b0, b1);
        }
    }
    // exp + transposed store + column-sum partials (no max needed: |att| < ~50)
    float* Et = g_E + (b * Nn + k0 + (ty << 3)) * Nn + n0;
#pragma unroll
    for (int i = 0; i < 8; i++) {
        float2 v0 = upk2(acc[i][0]), v1 = upk2(acc[i][1]);
        float2 v2 = upk2(acc[i][2]), v3 = upk2(acc[i][3]);
        float e0 = __expf(v0.x), e1 = __expf(v0.y);
        float e2 = __expf(v1.x), e3 = __expf(v1.y);
        float e4 = __expf(v2.x), e5 = __expf(v2.y);
        float e6 = __expf(v3.x), e7 = __expf(v3.y);
        *(float4*)&Et[i * Nn + (tx << 2)] = make_float4(e0, e1, e2, e3);
        *(float4*)&Et[i * Nn + 64 + (tx << 2)] = make_float4(e4, e5, e6, e7);
        red[(ty << 3) + i][tx] = e0 + e1 + e2 + e3 + e4 + e5 + e6 + e7;
    }
    __syncthreads();
    if (t < 128) {
        float s = 0.0f;
#pragma unroll
        for (int j = 0; j < 16; j++) s += red[t][j];
        atomicAdd(&g_Z[b * Nn + k0 + t], s);
    }
}

// ---------------- K5: gmz2[m][o] = (sum_c wmask[o][c] gm[c][m]) / Z[m] ------
__global__ __launch_bounds__(256) void k5_gmz(const float* __restrict__ wmask) {
    __shared__ __align__(16) float smG[64][68];
    __shared__ __align__(16) float smW[64][68];
    __shared__ float sz[64];
    int b = blockIdx.x, m0 = blockIdx.y << 6;
    int t = threadIdx.x;
    const float* gm = g_gm + (b << 6) * Nn;
#pragma unroll
    for (int i = 0; i < 4; i++) {
        int idx = t + (i << 8);
        int r = idx >> 4, c4 = idx & 15;
        *(float4*)&smG[r][c4 << 2] = *(const float4*)&gm[r * Nn + m0 + (c4 << 2)];
        *(float4*)&smW[r][c4 << 2] = *(const float4*)&wmask[r * 64 + (c4 << 2)];
    }
    if (t < 64) sz[t] = 1.0f / g_Z[b * Nn + m0 + t];
    __syncthreads();
    int m = t & 63, og = t >> 6;
    float inv = sz[m];
    float* dst = &g_gmz2[(b * Nn + m0 + m) * Cc + (og << 4)];
#pragma unroll
    for (int q = 0; q < 4; q++) {
        float r[4];
#pragma unroll
        for (int j = 0; j < 4; j++) {
            int o = (og << 4) + (q << 2) + j;
            float s = 0.0f;
#pragma unroll
            for (int c = 0; c < 64; c++) s += smW[o][c] * smG[c][m];
            r[j] = s * inv;
        }
        *(float4*)&dst[q << 2] = make_float4(r[0], r[1], r[2], r[3]);
    }
}

// ---------------- K4: out[o][n] = sum_m gmz2[m][o] * E_t[m][n] + x ----------
// grid (B, N/256), block 256, micro 8o x 8n
__global__ __launch_bounds__(256, 2) void k4_out(
    const float* __restrict__ x, float* __restrict__ out) {
    __shared__ __align__(16) float sG[32][68];   // [mm][o]
    __shared__ __align__(16) float sE[32][264];  // [mm][nn], n-tile 256
    int b = blockIdx.x, n0 = blockIdx.y << 8;
    int t = threadIdx.x, cy = t >> 5, nx = t & 31;

    ull acc[8][4] = {};
    for (int m0 = 0; m0 < Nn; m0 += 32) {
        __syncthreads();
#pragma unroll
        for (int i = 0; i < 2; i++) {
            int idx = t + (i << 8);
            int r = idx >> 4, c4 = idx & 15;
            *(float4*)&sG[r][c4 << 2] =
                *(const float4*)&g_gmz2[(b * Nn + m0 + r) * Cc + (c4 << 2)];
        }
#pragma unroll
        for (int i = 0; i < 8; i++) {
            int idx = t + (i << 8);
            int r = idx >> 6, c4 = idx & 63;
            *(float4*)&sE[r][c4 << 2] =
                *(const float4*)&g_E[(b * Nn + m0 + r) * Nn + n0 + (c4 << 2)];
        }
        __syncthreads();
#pragma unroll
        for (int mm = 0; mm < 32; mm++) {
            float4 a0 = *(const float4*)&sG[mm][cy << 3];
            float4 a1 = *(const float4*)&sG[mm][(cy << 3) + 4];
            ulonglong2 b0 = *(const ulonglong2*)&sE[mm][nx << 2];
            ulonglong2 b1 = *(const ulonglong2*)&sE[mm][128 + (nx << 2)];
            float kv[8] = {a0.x, a0.y, a0.z, a0.w, a1.x, a1.y, a1.z, a1.w};
            FMA_ROW8(acc, kv, b0, b1);
        }
    }
#pragma unroll
    for (int i = 0; i < 8; i++) {
        int c = (cy << 3) + i;
        int off = ((b << 6) + c) * Nn + n0 + (nx << 2);
        float2 v0 = upk2(acc[i][0]), v1 = upk2(acc[i][1]);
        float2 v2 = upk2(acc[i][2]), v3 = upk2(acc[i][3]);
        float4 x0 = *(const float4*)&x[off];
        float4 x1 = *(const float4*)&x[off + 128];
        *(float4*)&out[off] =
            make_float4(v0.x + x0.x, v0.y + x0.y, v1.x + x0.z, v1.y + x0.w);
        *(float4*)&out[off + 128] =
            make_float4(v2.x + x1.x, v2.y + x1.y, v3.x + x1.z, v3.y + x1.w);
    }
}

// ---------------- launch ----------------------------------------------------
extern "C" void kernel_launch(void* const* d_in, const int* in_sizes, int n_in,
                              void* d_out, int out_size) {
    const float* x      = (const float*)d_in[0];
    const float* wphi   = (const float*)d_in[1];
    const float* wtheta = (const float*)d_in[2];
    const float* wg     = (const float*)d_in[3];
    const float* wmask  = (const float*)d_in[4];
    const float* wmv    = (const float*)d_in[5];
    const float* wmk    = (const float*)d_in[6];
    float* out = (float*)d_out;

    k0_prep<<<128, 256>>>(wmv, wg);
    k0t_transpose<<<dim3(32, 32), 256>>>(wmk);
    k1_channel<<<dim3(32, 16), 256>>>(x, wphi, wtheta);
    k2_P<<<dim3(32, 4), 256>>>();
    k3_att<<<dim3(8, 8, 32), 256>>>();
    k5_gmz<<<dim3(32, 16), 256>>>(wmask);
    k4_out<<<dim3(32, 4), 256>>>(x, out);
}